// round 9
// baseline (speedup 1.0000x reference)
#include <cuda_runtime.h>
#include <cstdint>

#define T_STEPS 336
#define BATCH   4096
#define NFEAT   32
#define UN1     64
#define UN2     32
#define G1      256   // 4*UN1
#define G2      128   // 4*UN2
#define ROWS    32
#define THREADS 512
#define CTAS    (BATCH / ROWS)   // 128
#define RSTRIDE 128   // combined row: [x(32)|h1(64)|h2(32)]

// quad-split interleaved weights:
//  W1A[k][up] = float4{ w_i(2up), w_i(2up+1), w_f(2up), w_f(2up+1) }   (k = 0..95)
//  W1B[k][up] = gates g,o likewise.  Row stride 32 float4 = 128 floats.
//  W2A/W2B: 16 ups, row stride 64 floats.
#define WK1 128
#define WK2 64

// ---- shared memory layout (float offsets) ----
#define OFF_W1A 0
#define OFF_W1B (OFF_W1A + 96 * WK1)            // 12288
#define OFF_W2A (OFF_W1B + 96 * WK1)            // 24576
#define OFF_W2B (OFF_W2A + 96 * WK2)            // 30720
#define OFF_C   (OFF_W2B + 96 * WK2)            // 36864: 2 buffers x 32 x 128
#define SMEM_FLOATS (OFF_C + 2 * ROWS * RSTRIDE) // 45056 -> 180224 bytes

typedef unsigned long long ull;

// ---------------- packed f32x2 helpers ----------------
__device__ __forceinline__ ull pack2(float a) {
    ull r; asm("mov.b64 %0, {%1, %1};" : "=l"(r) : "f"(a)); return r;
}
__device__ __forceinline__ ull pakf2(float x, float y) {
    ull r; asm("mov.b64 %0, {%1, %2};" : "=l"(r) : "f"(x), "f"(y)); return r;
}
__device__ __forceinline__ ull fma2(ull a, ull b, ull c) {
    ull d; asm("fma.rn.f32x2 %0, %1, %2, %3;" : "=l"(d) : "l"(a), "l"(b), "l"(c)); return d;
}
__device__ __forceinline__ ull add2(ull a, ull b) {
    ull d; asm("add.rn.f32x2 %0, %1, %2;" : "=l"(d) : "l"(a), "l"(b)); return d;
}
__device__ __forceinline__ float2 unpack2(ull v) {
    float2 r; asm("mov.b64 {%0, %1}, %2;" : "=f"(r.x), "=f"(r.y) : "l"(v)); return r;
}

// ---------------- fast HW math ----------------
__device__ __forceinline__ float ex2a(float x) {
    float y; asm("ex2.approx.f32 %0, %1;" : "=f"(y) : "f"(x)); return y;
}
__device__ __forceinline__ float rcpa(float x) {
    float y; asm("rcp.approx.f32 %0, %1;" : "=f"(y) : "f"(x)); return y;
}

// Full LSTM pointwise update for one row (2 units), batched reciprocals:
// 10x EX2 + 2x RCP (vs 20 MUFU naive). Keras gates i,f,c(g),o.
__device__ __forceinline__ float2 lstm_act2(float2 zi, float2 zf, float2 zg, float2 zo,
                                            float& cc0, float& cc1) {
    const float NL2E  = -1.4426950408889634f;   // -log2(e)
    const float N2L2E = -2.8853900817779268f;   // -2*log2(e)
    float ei0 = ex2a(zi.x * NL2E), ei1 = ex2a(zi.y * NL2E);
    float ef0 = ex2a(zf.x * NL2E), ef1 = ex2a(zf.y * NL2E);
    float eg0 = ex2a(fabsf(zg.x) * N2L2E), eg1 = ex2a(fabsf(zg.y) * N2L2E);
    float eo0 = ex2a(zo.x * NL2E), eo1 = ex2a(zo.y * NL2E);
    float di0 = 1.f + ei0, di1 = 1.f + ei1;
    float df0 = 1.f + ef0, df1 = 1.f + ef1;
    float dg0 = 1.f + eg0, dg1 = 1.f + eg1;
    float do0 = 1.f + eo0, do1 = 1.f + eo1;
    float p01 = di0 * di1, p23 = df0 * df1, p45 = dg0 * dg1, p67 = do0 * do1;
    float q0 = p01 * p23, q1 = p45 * p67;
    float R  = rcpa(q0 * q1);
    float iq0 = R * q1, iq1 = R * q0;               // 1/q0, 1/q1
    float ip01 = iq0 * p23, ip23 = iq0 * p01;       // 1/p01, 1/p23
    float ip45 = iq1 * p67, ip67 = iq1 * p45;       // 1/p45, 1/p67
    float i0 = ip01 * di1, i1 = ip01 * di0;         // sigmoid(zi)
    float f0 = ip23 * df1, f1 = ip23 * df0;
    float go0 = ip45 * dg1, go1 = ip45 * dg0;       // 1/dg
    float o0 = ip67 * do1, o1 = ip67 * do0;
    float tg0 = copysignf((1.f - eg0) * go0, zg.x); // tanh(zg)
    float tg1 = copysignf((1.f - eg1) * go1, zg.y);
    cc0 = f0 * cc0 + i0 * tg0;
    cc1 = f1 * cc1 + i1 * tg1;
    float ec0 = ex2a(fabsf(cc0) * N2L2E), ec1 = ex2a(fabsf(cc1) * N2L2E);
    float dc0 = 1.f + ec0, dc1 = 1.f + ec1;
    float Rc = rcpa(dc0 * dc1);
    float tc0 = copysignf((1.f - ec0) * (Rc * dc1), cc0);
    float tc1 = copysignf((1.f - ec1) * (Rc * dc0), cc1);
    float2 h; h.x = o0 * tc0; h.y = o1 * tc1;
    return h;
}

// ---------------- cp.async helpers ----------------
__device__ __forceinline__ void cp16(uint32_t saddr, const float* g) {
    asm volatile("cp.async.cg.shared.global [%0], [%1], 16;" :: "r"(saddr), "l"(g));
}
__device__ __forceinline__ void cp_commit() { asm volatile("cp.async.commit_group;"); }
__device__ __forceinline__ void cp_wait0()  { asm volatile("cp.async.wait_group 0;" ::: "memory"); }

// 48-column panel: R rows x (2 units x 4 gates), quad-split weights:
// per k, one LDS.128 from wA (gates i,f) + one from wB (gates g,o).
template <int R, int WK>
__device__ __forceinline__ void panelQ(ull (&acc)[R][4],
                                       const float* __restrict__ in,
                                       const float* __restrict__ wA,
                                       const float* __restrict__ wB) {
#pragma unroll 2
    for (int k = 0; k < 48; k += 2) {
        float2 a[R];
#pragma unroll
        for (int r = 0; r < R; r++) a[r] = *(const float2*)(in + r * RSTRIDE + k);
        ulonglong2 qa = *(const ulonglong2*)(wA + k * WK);
        ulonglong2 qb = *(const ulonglong2*)(wB + k * WK);
#pragma unroll
        for (int r = 0; r < R; r++) {
            ull p = pack2(a[r].x);
            acc[r][0] = fma2(p, qa.x, acc[r][0]);
            acc[r][1] = fma2(p, qa.y, acc[r][1]);
            acc[r][2] = fma2(p, qb.x, acc[r][2]);
            acc[r][3] = fma2(p, qb.y, acc[r][3]);
        }
        qa = *(const ulonglong2*)(wA + (k + 1) * WK);
        qb = *(const ulonglong2*)(wB + (k + 1) * WK);
#pragma unroll
        for (int r = 0; r < R; r++) {
            ull p = pack2(a[r].y);
            acc[r][0] = fma2(p, qa.x, acc[r][0]);
            acc[r][1] = fma2(p, qa.y, acc[r][1]);
            acc[r][2] = fma2(p, qb.x, acc[r][2]);
            acc[r][3] = fma2(p, qb.y, acc[r][3]);
        }
    }
}

__global__ void __launch_bounds__(THREADS, 1)
lstm_fused_kernel(const float* __restrict__ x,
                  const float* __restrict__ W1, const float* __restrict__ U1w, const float* __restrict__ b1,
                  const float* __restrict__ W2, const float* __restrict__ U2w, const float* __restrict__ b2,
                  const float* __restrict__ Wv, const float* __restrict__ bv,
                  const float* __restrict__ Wo, const float* __restrict__ bo,
                  const float* __restrict__ Wd1, const float* __restrict__ bd1,
                  const float* __restrict__ Wd2, const float* __restrict__ bd2,
                  float* __restrict__ out) {
    extern __shared__ float sm[];
    const int tid = threadIdx.x;
    const int b0  = blockIdx.x * ROWS;

    // ---- stage weights into quad-split interleaved SMEM arrays (one time) ----
    // L1: stacked [W1;U1] rows k=0..95, 32 unit pairs
    for (int idx = tid; idx < 96 * 32; idx += THREADS) {
        int k = idx >> 5, u = idx & 31;
        const float* src = (k < NFEAT) ? (W1 + k * G1) : (U1w + (k - NFEAT) * G1);
        float4 qa = make_float4(src[2 * u], src[2 * u + 1],
                                src[UN1 + 2 * u], src[UN1 + 2 * u + 1]);
        float4 qb = make_float4(src[2 * UN1 + 2 * u], src[2 * UN1 + 2 * u + 1],
                                src[3 * UN1 + 2 * u], src[3 * UN1 + 2 * u + 1]);
        ((float4*)(sm + OFF_W1A))[k * 32 + u] = qa;
        ((float4*)(sm + OFF_W1B))[k * 32 + u] = qb;
    }
    // L2: stacked [W2;U2] rows k=0..95, 16 unit pairs
    for (int idx = tid; idx < 96 * 16; idx += THREADS) {
        int k = idx >> 4, u = idx & 15;
        const float* src = (k < UN1) ? (W2 + k * G2) : (U2w + (k - UN1) * G2);
        float4 qa = make_float4(src[2 * u], src[2 * u + 1],
                                src[UN2 + 2 * u], src[UN2 + 2 * u + 1]);
        float4 qb = make_float4(src[2 * UN2 + 2 * u], src[2 * UN2 + 2 * u + 1],
                                src[3 * UN2 + 2 * u], src[3 * UN2 + 2 * u + 1]);
        ((float4*)(sm + OFF_W2A))[k * 16 + u] = qa;
        ((float4*)(sm + OFF_W2B))[k * 16 + u] = qb;
    }
    // zero both combined state buffers
    for (int i = tid; i < 2 * ROWS * RSTRIDE; i += THREADS) sm[OFF_C + i] = 0.0f;

    // ---- thread mapping (R5): warps 0-7 = L1 (8-row tiles), warps 8-15 = L2 (4-row) ----
    const bool isL1 = (tid < 256);
    const int wg = (tid & 255) >> 5;
    const int l  = tid & 31;
    const int kh = l >> 4;                        // K-half
    const int rg  = wg & 3;                       // L1 row group (8 rows)
    const int up  = (l & 15) | ((wg >> 2) << 4);  // L1 unit pair 0..31
    const int rg2 = wg;                           // L2 row group (4 rows)
    const int up2 = l & 15;                       // L2 unit pair 0..15

    // bias -> registers (kh==0 half carries it; partner contributes 0)
    ull bq[4];
    if (isL1) {
#pragma unroll
        for (int g = 0; g < 4; g++) {
            float2 bb = (kh == 0) ? *(const float2*)(b1 + g * UN1 + 2 * up)
                                  : make_float2(0.f, 0.f);
            bq[g] = pakf2(bb.x, bb.y);
        }
    } else {
#pragma unroll
        for (int g = 0; g < 4; g++) {
            float2 bb = (kh == 0) ? *(const float2*)(b2 + g * UN2 + 2 * up2)
                                  : make_float2(0.f, 0.f);
            bq[g] = pakf2(bb.x, bb.y);
        }
    }

    float c1[4][2], c2[2][2];
#pragma unroll
    for (int r = 0; r < 4; r++) { c1[r][0] = c1[r][1] = 0.0f; }
#pragma unroll
    for (int r = 0; r < 2; r++) { c2[r][0] = c2[r][1] = 0.0f; }

    // ---- x prefetch: threads 0-255 move one float4 per step ----
    const bool xmover = (tid < 256);
    const int xrow = tid >> 3;
    const int xq   = tid & 7;
    const float* xg = x + ((size_t)(b0 + xrow) * T_STEPS) * NFEAT + xq * 4;
    uint32_t sx0 = (uint32_t)__cvta_generic_to_shared(sm + OFF_C + xrow * RSTRIDE + xq * 4);
    const uint32_t cbufbytes = ROWS * RSTRIDE * 4;

    __syncthreads();                    // zeroing visible before cp.async writes x
    if (xmover) cp16(sx0, xg);          // x_0 -> buffer 0
    cp_commit();

    const float* wA1 = sm + OFF_W1A + (kh * 48) * WK1 + up * 4;
    const float* wB1 = sm + OFF_W1B + (kh * 48) * WK1 + up * 4;
    const float* wA2 = sm + OFF_W2A + (kh * 48) * WK2 + up2 * 4;
    const float* wB2 = sm + OFF_W2B + (kh * 48) * WK2 + up2 * 4;

    // Iter t: L1 computes step t (t<T), L2 computes step t-1 (t>=1). One barrier/step.
    for (int t = 0; t <= T_STEPS; ++t) {
        if (t < T_STEPS) cp_wait0();
        __syncthreads();
        if (t + 1 < T_STEPS && xmover)
            cp16(sx0 + ((t + 1) & 1) * cbufbytes, xg + (size_t)(t + 1) * NFEAT);
        cp_commit();
        const int rb = t & 1;
        const float* cin  = sm + OFF_C + rb * (ROWS * RSTRIDE);
        float*       cout = sm + OFF_C + (rb ^ 1) * (ROWS * RSTRIDE);

        if (isL1) {
            if (t < T_STEPS) {
                ull acc[8][4];
#pragma unroll
                for (int r = 0; r < 8; r++)
#pragma unroll
                    for (int g = 0; g < 4; g++) acc[r][g] = bq[g];

                // gate K-rows [x|h1] = cin cols 0..95; this thread: cols kh*48..+47
                panelQ<8, WK1>(acc, cin + rg * 8 * RSTRIDE + kh * 48, wA1, wB1);

                // half-exchange reduction: results land in acc[0..3]
#pragma unroll
                for (int r = 0; r < 4; r++)
#pragma unroll
                    for (int g = 0; g < 4; g++) {
                        ull send = acc[(1 - kh) * 4 + r][g];
                        ull recv = __shfl_xor_sync(0xffffffffu, send, 16);
                        acc[r][g] = add2(acc[kh * 4 + r][g], recv);
                    }

#pragma unroll
                for (int r = 0; r < 4; r++) {
                    float2 h = lstm_act2(unpack2(acc[r][0]), unpack2(acc[r][1]),
                                         unpack2(acc[r][2]), unpack2(acc[r][3]),
                                         c1[r][0], c1[r][1]);
                    *(float2*)(cout + (rg * 8 + kh * 4 + r) * RSTRIDE + 32 + 2 * up) = h;
                }
            }
        } else {
            if (t >= 1) {
                ull acc2[4][4];
#pragma unroll
                for (int r = 0; r < 4; r++)
#pragma unroll
                    for (int g = 0; g < 4; g++) acc2[r][g] = bq[g];

                // gate K-rows [h1(t-1)|h2(t-2)] = cin cols 32..127; this thread: 32+kh*48..+47
                panelQ<4, WK2>(acc2, cin + rg2 * 4 * RSTRIDE + 32 + kh * 48, wA2, wB2);

#pragma unroll
                for (int r = 0; r < 2; r++)
#pragma unroll
                    for (int g = 0; g < 4; g++) {
                        ull send = acc2[(1 - kh) * 2 + r][g];
                        ull recv = __shfl_xor_sync(0xffffffffu, send, 16);
                        acc2[r][g] = add2(acc2[kh * 2 + r][g], recv);
                    }

#pragma unroll
                for (int r = 0; r < 2; r++) {
                    float2 h = lstm_act2(unpack2(acc2[r][0]), unpack2(acc2[r][1]),
                                         unpack2(acc2[r][2]), unpack2(acc2[r][3]),
                                         c2[r][0], c2[r][1]);
                    *(float2*)(cout + (rg2 * 4 + kh * 2 + r) * RSTRIDE + 96 + 2 * up2) = h;
                }
            }
        }
    }
    __syncthreads();

    // final h2 = h2(T-1), written at iter t=T into buf ((T&1)^1)
    const float* h2f = sm + OFF_C + ((T_STEPS & 1) ^ 1) * (ROWS * RSTRIDE) + 96;

    // ============ head: MHA(seq=1) == identity-attention -> v@Wo, then MLP ============
    float* sv  = sm;            // scratch in dead weight region
    float* so  = sm + 1024;
    float* sd1 = sm + 2048;
    for (int idx = tid; idx < ROWS * 32; idx += THREADS) {
        int r = idx >> 5, j = idx & 31;
        float s = bv[j];
        const float* h2row = h2f + r * RSTRIDE;
#pragma unroll
        for (int d = 0; d < 32; d++) s += h2row[d] * Wv[d * 32 + j];
        sv[idx] = s;
    }
    __syncthreads();
    for (int idx = tid; idx < ROWS * 32; idx += THREADS) {
        int r = idx >> 5, e = idx & 31;
        float s = bo[e];
#pragma unroll
        for (int j = 0; j < 32; j++) s += sv[r * 32 + j] * Wo[j * 32 + e];
        so[idx] = s;
    }
    __syncthreads();
    for (int idx = tid; idx < ROWS * 64; idx += THREADS) {
        int r = idx >> 6, m = idx & 63;
        float s = bd1[m];
#pragma unroll
        for (int e = 0; e < 32; e++) s += so[r * 32 + e] * Wd1[e * 64 + m];
        sd1[idx] = fmaxf(s, 0.0f);
    }
    __syncthreads();
    for (int idx = tid; idx < ROWS * 24; idx += THREADS) {
        int r = idx / 24, p = idx % 24;
        float s = bd2[p];
#pragma unroll
        for (int m = 0; m < 64; m++) s += sd1[r * 64 + m] * Wd2[m * 24 + p];
        out[(size_t)(b0 + r) * 24 + p] = s;
    }
}

extern "C" void kernel_launch(void* const* d_in, const int* in_sizes, int n_in,
                              void* d_out, int out_size) {
    const float* x   = (const float*)d_in[0];
    const float* W1  = (const float*)d_in[1];
    const float* U1w = (const float*)d_in[2];
    const float* b1  = (const float*)d_in[3];
    const float* W2  = (const float*)d_in[4];
    const float* U2w = (const float*)d_in[5];
    const float* b2  = (const float*)d_in[6];
    // d_in[7..10] = Wq, bq, Wk, bk: dead (softmax over seq-len 1 == 1)
    const float* Wv  = (const float*)d_in[11];
    const float* bv  = (const float*)d_in[12];
    const float* Wo  = (const float*)d_in[13];
    const float* bo  = (const float*)d_in[14];
    const float* Wd1 = (const float*)d_in[15];
    const float* bd1 = (const float*)d_in[16];
    const float* Wd2 = (const float*)d_in[17];
    const float* bd2 = (const float*)d_in[18];

    size_t smem = SMEM_FLOATS * sizeof(float);   // 180224 B
    cudaFuncSetAttribute(lstm_fused_kernel,
                         cudaFuncAttributeMaxDynamicSharedMemorySize, (int)smem);
    lstm_fused_kernel<<<CTAS, THREADS, smem>>>(
        x, W1, U1w, b1, W2, U2w, b2, Wv, bv, Wo, bo, Wd1, bd1, Wd2, bd2,
        (float*)d_out);
}

// round 10
// speedup vs baseline: 1.5184x; 1.5184x over previous
#include <cuda_runtime.h>
#include <cstdint>

#define T_STEPS 336
#define BATCH   4096
#define NFEAT   32
#define UN1     64
#define UN2     32
#define G1      256   // 4*UN1
#define G2      128   // 4*UN2
#define ROWS    32
#define THREADS 512
#define CTAS    (BATCH / ROWS)   // 128
#define RSTRIDE 128   // combined row: [x(32)|h1(64)|h2(32)]

// quad-split interleaved weights:
//  W1A[k][up] = float4{ w_i(2up), w_i(2up+1), w_f(2up), w_f(2up+1) }   (k = 0..95)
//  W1B[k][up] = gates g,o likewise. Row stride WK1 floats.
#define WK1 128
#define WK2 64

// ---- shared memory layout (float offsets) ----
#define OFF_W1A 0
#define OFF_W1B (OFF_W1A + 96 * WK1)            // 12288
#define OFF_W2A (OFF_W1B + 96 * WK1)            // 24576
#define OFF_W2B (OFF_W2A + 96 * WK2)            // 30720
#define OFF_C   (OFF_W2B + 96 * WK2)            // 36864: 2 buffers x 32 x 128
#define SMEM_FLOATS (OFF_C + 2 * ROWS * RSTRIDE) // 45056 -> 180224 bytes

typedef unsigned long long ull;

// ---------------- packed f32x2 helpers ----------------
__device__ __forceinline__ ull pack2(float a) {
    ull r; asm("mov.b64 %0, {%1, %1};" : "=l"(r) : "f"(a)); return r;
}
__device__ __forceinline__ ull pakf2(float x, float y) {
    ull r; asm("mov.b64 %0, {%1, %2};" : "=l"(r) : "f"(x), "f"(y)); return r;
}
__device__ __forceinline__ ull fma2(ull a, ull b, ull c) {
    ull d; asm("fma.rn.f32x2 %0, %1, %2, %3;" : "=l"(d) : "l"(a), "l"(b), "l"(c)); return d;
}
__device__ __forceinline__ ull add2(ull a, ull b) {
    ull d; asm("add.rn.f32x2 %0, %1, %2;" : "=l"(d) : "l"(a), "l"(b)); return d;
}
__device__ __forceinline__ float2 unpack2(ull v) {
    float2 r; asm("mov.b64 {%0, %1}, %2;" : "=f"(r.x), "=f"(r.y) : "l"(v)); return r;
}

// ---------------- fast HW math ----------------
__device__ __forceinline__ float ex2a(float x) {
    float y; asm("ex2.approx.f32 %0, %1;" : "=f"(y) : "f"(x)); return y;
}
__device__ __forceinline__ float rcpa(float x) {
    float y; asm("rcp.approx.f32 %0, %1;" : "=f"(y) : "f"(x)); return y;
}

// Full LSTM pointwise update, one row (2 units), batched reciprocals:
// 10x EX2 + 2x RCP (vs 20 MUFU naive). Keras gate order i,f,c(g),o.
__device__ __forceinline__ float2 lstm_act2(float2 zi, float2 zf, float2 zg, float2 zo,
                                            float& cc0, float& cc1) {
    const float NL2E  = -1.4426950408889634f;   // -log2(e)
    const float N2L2E = -2.8853900817779268f;   // -2*log2(e)
    float ei0 = ex2a(zi.x * NL2E), ei1 = ex2a(zi.y * NL2E);
    float ef0 = ex2a(zf.x * NL2E), ef1 = ex2a(zf.y * NL2E);
    float eg0 = ex2a(fabsf(zg.x) * N2L2E), eg1 = ex2a(fabsf(zg.y) * N2L2E);
    float eo0 = ex2a(zo.x * NL2E), eo1 = ex2a(zo.y * NL2E);
    float di0 = 1.f + ei0, di1 = 1.f + ei1;
    float df0 = 1.f + ef0, df1 = 1.f + ef1;
    float dg0 = 1.f + eg0, dg1 = 1.f + eg1;
    float do0 = 1.f + eo0, do1 = 1.f + eo1;
    float p01 = di0 * di1, p23 = df0 * df1, p45 = dg0 * dg1, p67 = do0 * do1;
    float q0 = p01 * p23, q1 = p45 * p67;
    float R  = rcpa(q0 * q1);
    float iq0 = R * q1, iq1 = R * q0;               // 1/q0, 1/q1
    float ip01 = iq0 * p23, ip23 = iq0 * p01;       // 1/p01, 1/p23
    float ip45 = iq1 * p67, ip67 = iq1 * p45;       // 1/p45, 1/p67
    float i0 = ip01 * di1, i1 = ip01 * di0;         // sigmoid(zi)
    float f0 = ip23 * df1, f1 = ip23 * df0;
    float go0 = ip45 * dg1, go1 = ip45 * dg0;       // 1/dg
    float o0 = ip67 * do1, o1 = ip67 * do0;
    float tg0 = copysignf((1.f - eg0) * go0, zg.x); // tanh(zg)
    float tg1 = copysignf((1.f - eg1) * go1, zg.y);
    cc0 = f0 * cc0 + i0 * tg0;
    cc1 = f1 * cc1 + i1 * tg1;
    float ec0 = ex2a(fabsf(cc0) * N2L2E), ec1 = ex2a(fabsf(cc1) * N2L2E);
    float dc0 = 1.f + ec0, dc1 = 1.f + ec1;
    float Rc = rcpa(dc0 * dc1);
    float tc0 = copysignf((1.f - ec0) * (Rc * dc1), cc0);
    float tc1 = copysignf((1.f - ec1) * (Rc * dc0), cc1);
    float2 h; h.x = o0 * tc0; h.y = o1 * tc1;
    return h;
}

// ---------------- cp.async helpers ----------------
__device__ __forceinline__ void cp16(uint32_t saddr, const float* g) {
    asm volatile("cp.async.cg.shared.global [%0], [%1], 16;" :: "r"(saddr), "l"(g));
}
__device__ __forceinline__ void cp_commit() { asm volatile("cp.async.commit_group;"); }
__device__ __forceinline__ void cp_wait0()  { asm volatile("cp.async.wait_group 0;" ::: "memory"); }

// 48-column panel: R rows x (2 units x 4 gates), quad-split weights:
// per k, one LDS.128 from wA (gates i,f) + one from wB (gates g,o).
template <int R, int WK>
__device__ __forceinline__ void panelQ(ull (&acc)[R][4],
                                       const float* __restrict__ in,
                                       const float* __restrict__ wA,
                                       const float* __restrict__ wB) {
#pragma unroll 2
    for (int k = 0; k < 48; k += 2) {
        float2 a[R];
#pragma unroll
        for (int r = 0; r < R; r++) a[r] = *(const float2*)(in + r * RSTRIDE + k);
        ulonglong2 qa = *(const ulonglong2*)(wA + k * WK);
        ulonglong2 qb = *(const ulonglong2*)(wB + k * WK);
#pragma unroll
        for (int r = 0; r < R; r++) {
            ull p = pack2(a[r].x);
            acc[r][0] = fma2(p, qa.x, acc[r][0]);
            acc[r][1] = fma2(p, qa.y, acc[r][1]);
            acc[r][2] = fma2(p, qb.x, acc[r][2]);
            acc[r][3] = fma2(p, qb.y, acc[r][3]);
        }
        qa = *(const ulonglong2*)(wA + (k + 1) * WK);
        qb = *(const ulonglong2*)(wB + (k + 1) * WK);
#pragma unroll
        for (int r = 0; r < R; r++) {
            ull p = pack2(a[r].y);
            acc[r][0] = fma2(p, qa.x, acc[r][0]);
            acc[r][1] = fma2(p, qa.y, acc[r][1]);
            acc[r][2] = fma2(p, qb.x, acc[r][2]);
            acc[r][3] = fma2(p, qb.y, acc[r][3]);
        }
    }
}

__global__ void __launch_bounds__(THREADS, 1)
lstm_fused_kernel(const float* __restrict__ x,
                  const float* __restrict__ W1, const float* __restrict__ U1w, const float* __restrict__ b1,
                  const float* __restrict__ W2, const float* __restrict__ U2w, const float* __restrict__ b2,
                  const float* __restrict__ Wv, const float* __restrict__ bv,
                  const float* __restrict__ Wo, const float* __restrict__ bo,
                  const float* __restrict__ Wd1, const float* __restrict__ bd1,
                  const float* __restrict__ Wd2, const float* __restrict__ bd2,
                  float* __restrict__ out) {
    extern __shared__ float sm[];
    const int tid = threadIdx.x;
    const int b0  = blockIdx.x * ROWS;

    // ---- stage weights into quad-split interleaved SMEM arrays (one time) ----
    for (int idx = tid; idx < 96 * 32; idx += THREADS) {
        int k = idx >> 5, u = idx & 31;
        const float* src = (k < NFEAT) ? (W1 + k * G1) : (U1w + (k - NFEAT) * G1);
        float4 qa = make_float4(src[2 * u], src[2 * u + 1],
                                src[UN1 + 2 * u], src[UN1 + 2 * u + 1]);
        float4 qb = make_float4(src[2 * UN1 + 2 * u], src[2 * UN1 + 2 * u + 1],
                                src[3 * UN1 + 2 * u], src[3 * UN1 + 2 * u + 1]);
        ((float4*)(sm + OFF_W1A))[k * 32 + u] = qa;
        ((float4*)(sm + OFF_W1B))[k * 32 + u] = qb;
    }
    for (int idx = tid; idx < 96 * 16; idx += THREADS) {
        int k = idx >> 4, u = idx & 15;
        const float* src = (k < UN1) ? (W2 + k * G2) : (U2w + (k - UN1) * G2);
        float4 qa = make_float4(src[2 * u], src[2 * u + 1],
                                src[UN2 + 2 * u], src[UN2 + 2 * u + 1]);
        float4 qb = make_float4(src[2 * UN2 + 2 * u], src[2 * UN2 + 2 * u + 1],
                                src[3 * UN2 + 2 * u], src[3 * UN2 + 2 * u + 1]);
        ((float4*)(sm + OFF_W2A))[k * 16 + u] = qa;
        ((float4*)(sm + OFF_W2B))[k * 16 + u] = qb;
    }
    for (int i = tid; i < 2 * ROWS * RSTRIDE; i += THREADS) sm[OFF_C + i] = 0.0f;

    // ---- thread mapping (R5): warps 0-7 = L1 (8-row tiles), warps 8-15 = L2 (4-row) ----
    const bool isL1 = (tid < 256);
    const int wg = (tid & 255) >> 5;
    const int l  = tid & 31;
    const int kh = l >> 4;                        // K-half
    const int rg  = wg & 3;                       // L1 row group (8 rows)
    const int up  = (l & 15) | ((wg >> 2) << 4);  // L1 unit pair 0..31
    const int rg2 = wg;                           // L2 row group (4 rows)
    const int up2 = l & 15;                       // L2 unit pair 0..15

    // bias -> registers (kh==0 half carries it; partner contributes 0)
    ull bq[4];
    if (isL1) {
#pragma unroll
        for (int g = 0; g < 4; g++) {
            float2 bb = (kh == 0) ? *(const float2*)(b1 + g * UN1 + 2 * up)
                                  : make_float2(0.f, 0.f);
            bq[g] = pakf2(bb.x, bb.y);
        }
    } else {
#pragma unroll
        for (int g = 0; g < 4; g++) {
            float2 bb = (kh == 0) ? *(const float2*)(b2 + g * UN2 + 2 * up2)
                                  : make_float2(0.f, 0.f);
            bq[g] = pakf2(bb.x, bb.y);
        }
    }

    float c1[4][2], c2[2][2];
#pragma unroll
    for (int r = 0; r < 4; r++) { c1[r][0] = c1[r][1] = 0.0f; }
#pragma unroll
    for (int r = 0; r < 2; r++) { c2[r][0] = c2[r][1] = 0.0f; }

    // ---- x prefetch: threads 0-255 move one float4 per step ----
    const bool xmover = (tid < 256);
    const int xrow = tid >> 3;
    const int xq   = tid & 7;
    const float* xg = x + ((size_t)(b0 + xrow) * T_STEPS) * NFEAT + xq * 4;
    uint32_t sx0 = (uint32_t)__cvta_generic_to_shared(sm + OFF_C + xrow * RSTRIDE + xq * 4);
    const uint32_t cbufbytes = ROWS * RSTRIDE * 4;

    __syncthreads();                    // zeroing visible before cp.async writes x
    if (xmover) cp16(sx0, xg);          // x_0 -> buffer 0
    cp_commit();

    const float* wA1 = sm + OFF_W1A + (kh * 48) * WK1 + up * 4;
    const float* wB1 = sm + OFF_W1B + (kh * 48) * WK1 + up * 4;
    const float* wA2 = sm + OFF_W2A + (kh * 48) * WK2 + up2 * 4;
    const float* wB2 = sm + OFF_W2B + (kh * 48) * WK2 + up2 * 4;

    // Iter t: L1 computes step t (t<T), L2 computes step t-1 (t>=1). One barrier/step.
    for (int t = 0; t <= T_STEPS; ++t) {
        if (t < T_STEPS) cp_wait0();
        __syncthreads();
        if (t + 1 < T_STEPS && xmover)
            cp16(sx0 + ((t + 1) & 1) * cbufbytes, xg + (size_t)(t + 1) * NFEAT);
        cp_commit();
        const int rb = t & 1;
        const float* cin  = sm + OFF_C + rb * (ROWS * RSTRIDE);
        float*       cout = sm + OFF_C + (rb ^ 1) * (ROWS * RSTRIDE);

        if (isL1) {
            if (t < T_STEPS) {
                ull acc[8][4];
#pragma unroll
                for (int r = 0; r < 8; r++)
#pragma unroll
                    for (int g = 0; g < 4; g++) acc[r][g] = bq[g];

                // gate K-rows [x|h1] = cin cols 0..95; this thread: cols kh*48..+47
                panelQ<8, WK1>(acc, cin + rg * 8 * RSTRIDE + kh * 48, wA1, wB1);

                // R5-style symmetric K-split reduction (static indexing, no spills)
#pragma unroll
                for (int r = 0; r < 8; r++)
#pragma unroll
                    for (int g = 0; g < 4; g++)
                        acc[r][g] = add2(acc[r][g], __shfl_xor_sync(0xffffffffu, acc[r][g], 16));

                // kh=0 activates rows 0..3; kh=1 rows 4..7
#pragma unroll
                for (int r = 0; r < 4; r++) {
                    float2 zi = unpack2(kh ? acc[r + 4][0] : acc[r][0]);
                    float2 zf = unpack2(kh ? acc[r + 4][1] : acc[r][1]);
                    float2 zg = unpack2(kh ? acc[r + 4][2] : acc[r][2]);
                    float2 zo = unpack2(kh ? acc[r + 4][3] : acc[r][3]);
                    float2 h = lstm_act2(zi, zf, zg, zo, c1[r][0], c1[r][1]);
                    *(float2*)(cout + (rg * 8 + kh * 4 + r) * RSTRIDE + 32 + 2 * up) = h;
                }
            }
        } else {
            if (t >= 1) {
                ull acc2[4][4];
#pragma unroll
                for (int r = 0; r < 4; r++)
#pragma unroll
                    for (int g = 0; g < 4; g++) acc2[r][g] = bq[g];

                // gate K-rows [h1(t-1)|h2(t-2)] = cin cols 32..127; this thread: 32+kh*48..+47
                panelQ<4, WK2>(acc2, cin + rg2 * 4 * RSTRIDE + 32 + kh * 48, wA2, wB2);

#pragma unroll
                for (int r = 0; r < 4; r++)
#pragma unroll
                    for (int g = 0; g < 4; g++)
                        acc2[r][g] = add2(acc2[r][g], __shfl_xor_sync(0xffffffffu, acc2[r][g], 16));

#pragma unroll
                for (int r = 0; r < 2; r++) {
                    float2 zi = unpack2(kh ? acc2[r + 2][0] : acc2[r][0]);
                    float2 zf = unpack2(kh ? acc2[r + 2][1] : acc2[r][1]);
                    float2 zg = unpack2(kh ? acc2[r + 2][2] : acc2[r][2]);
                    float2 zo = unpack2(kh ? acc2[r + 2][3] : acc2[r][3]);
                    float2 h = lstm_act2(zi, zf, zg, zo, c2[r][0], c2[r][1]);
                    *(float2*)(cout + (rg2 * 4 + kh * 2 + r) * RSTRIDE + 96 + 2 * up2) = h;
                }
            }
        }
    }
    __syncthreads();

    // final h2 = h2(T-1), written at iter t=T into buf ((T&1)^1)
    const float* h2f = sm + OFF_C + ((T_STEPS & 1) ^ 1) * (ROWS * RSTRIDE) + 96;

    // ============ head: MHA(seq=1) == identity-attention -> v@Wo, then MLP ============
    float* sv  = sm;            // scratch in dead weight region
    float* so  = sm + 1024;
    float* sd1 = sm + 2048;
    for (int idx = tid; idx < ROWS * 32; idx += THREADS) {
        int r = idx >> 5, j = idx & 31;
        float s = bv[j];
        const float* h2row = h2f + r * RSTRIDE;
#pragma unroll
        for (int d = 0; d < 32; d++) s += h2row[d] * Wv[d * 32 + j];
        sv[idx] = s;
    }
    __syncthreads();
    for (int idx = tid; idx < ROWS * 32; idx += THREADS) {
        int r = idx >> 5, e = idx & 31;
        float s = bo[e];
#pragma unroll
        for (int j = 0; j < 32; j++) s += sv[r * 32 + j] * Wo[j * 32 + e];
        so[idx] = s;
    }
    __syncthreads();
    for (int idx = tid; idx < ROWS * 64; idx += THREADS) {
        int r = idx >> 6, m = idx & 63;
        float s = bd1[m];
#pragma unroll
        for (int e = 0; e < 32; e++) s += so[r * 32 + e] * Wd1[e * 64 + m];
        sd1[idx] = fmaxf(s, 0.0f);
    }
    __syncthreads();
    for (int idx = tid; idx < ROWS * 24; idx += THREADS) {
        int r = idx / 24, p = idx % 24;
        float s = bd2[p];
#pragma unroll
        for (int m = 0; m < 64; m++) s += sd1[r * 64 + m] * Wd2[m * 24 + p];
        out[(size_t)(b0 + r) * 24 + p] = s;
    }
}

extern "C" void kernel_launch(void* const* d_in, const int* in_sizes, int n_in,
                              void* d_out, int out_size) {
    const float* x   = (const float*)d_in[0];
    const float* W1  = (const float*)d_in[1];
    const float* U1w = (const float*)d_in[2];
    const float* b1  = (const float*)d_in[3];
    const float* W2  = (const float*)d_in[4];
    const float* U2w = (const float*)d_in[5];
    const float* b2  = (const float*)d_in[6];
    // d_in[7..10] = Wq, bq, Wk, bk: dead (softmax over seq-len 1 == 1)
    const float* Wv  = (const float*)d_in[11];
    const float* bv  = (const float*)d_in[12];
    const float* Wo  = (const float*)d_in[13];
    const float* bo  = (const float*)d_in[14];
    const float* Wd1 = (const float*)d_in[15];
    const float* bd1 = (const float*)d_in[16];
    const float* Wd2 = (const float*)d_in[17];
    const float* bd2 = (const float*)d_in[18];

    size_t smem = SMEM_FLOATS * sizeof(float);   // 180224 B
    cudaFuncSetAttribute(lstm_fused_kernel,
                         cudaFuncAttributeMaxDynamicSharedMemorySize, (int)smem);
    lstm_fused_kernel<<<CTAS, THREADS, smem>>>(
        x, W1, U1w, b1, W2, U2w, b2, Wv, bv, Wo, bo, Wd1, bd1, Wd2, bd2,
        (float*)d_out);
}

// round 11
// speedup vs baseline: 1.6024x; 1.0553x over previous
#include <cuda_runtime.h>
#include <cstdint>

#define T_STEPS 336
#define BATCH   4096
#define NFEAT   32
#define UN1     64
#define UN2     32
#define G1      256   // 4*UN1
#define G2      128   // 4*UN2
#define ROWS    32
#define THREADS 512
#define CTAS    (BATCH / ROWS)   // 128
#define RSTRIDE 128   // combined row: [x(32)|h1(64)|h2(32)]

// quad-split interleaved weights (R10-proven):
//  W1A[k][up] = float4{ w_i(2up), w_i(2up+1), w_f(2up), w_f(2up+1) }   (k = 0..95)
//  W1B[k][up] = gates g,o likewise. Row stride WK1 floats.
#define WK1 128
#define WK2 64

// ---- shared memory layout (float offsets) ----
#define OFF_W1A 0
#define OFF_W1B (OFF_W1A + 96 * WK1)            // 12288
#define OFF_W2A (OFF_W1B + 96 * WK1)            // 24576
#define OFF_W2B (OFF_W2A + 96 * WK2)            // 30720
#define OFF_C   (OFF_W2B + 96 * WK2)            // 36864: 2 buffers x 32 x 128
#define SMEM_FLOATS (OFF_C + 2 * ROWS * RSTRIDE) // 45056 -> 180224 bytes

typedef unsigned long long ull;

// ---------------- packed f32x2 helpers ----------------
__device__ __forceinline__ ull pack2(float a) {
    ull r; asm("mov.b64 %0, {%1, %1};" : "=l"(r) : "f"(a)); return r;
}
__device__ __forceinline__ ull pakf2(float x, float y) {
    ull r; asm("mov.b64 %0, {%1, %2};" : "=l"(r) : "f"(x), "f"(y)); return r;
}
__device__ __forceinline__ ull fma2(ull a, ull b, ull c) {
    ull d; asm("fma.rn.f32x2 %0, %1, %2, %3;" : "=l"(d) : "l"(a), "l"(b), "l"(c)); return d;
}
__device__ __forceinline__ ull add2(ull a, ull b) {
    ull d; asm("add.rn.f32x2 %0, %1, %2;" : "=l"(d) : "l"(a), "l"(b)); return d;
}
__device__ __forceinline__ float2 unpack2(ull v) {
    float2 r; asm("mov.b64 {%0, %1}, %2;" : "=f"(r.x), "=f"(r.y) : "l"(v)); return r;
}

// ---------------- fast HW math ----------------
__device__ __forceinline__ float ex2a(float x) {
    float y; asm("ex2.approx.f32 %0, %1;" : "=f"(y) : "f"(x)); return y;
}
__device__ __forceinline__ float rcpa(float x) {
    float y; asm("rcp.approx.f32 %0, %1;" : "=f"(y) : "f"(x)); return y;
}

// Full LSTM pointwise update, one row (2 units), batched reciprocals (R10-proven):
// 10x EX2 + 2x RCP. Keras gate order i,f,c(g),o.
__device__ __forceinline__ float2 lstm_act2(float2 zi, float2 zf, float2 zg, float2 zo,
                                            float& cc0, float& cc1) {
    const float NL2E  = -1.4426950408889634f;   // -log2(e)
    const float N2L2E = -2.8853900817779268f;   // -2*log2(e)
    float ei0 = ex2a(zi.x * NL2E), ei1 = ex2a(zi.y * NL2E);
    float ef0 = ex2a(zf.x * NL2E), ef1 = ex2a(zf.y * NL2E);
    float eg0 = ex2a(fabsf(zg.x) * N2L2E), eg1 = ex2a(fabsf(zg.y) * N2L2E);
    float eo0 = ex2a(zo.x * NL2E), eo1 = ex2a(zo.y * NL2E);
    float di0 = 1.f + ei0, di1 = 1.f + ei1;
    float df0 = 1.f + ef0, df1 = 1.f + ef1;
    float dg0 = 1.f + eg0, dg1 = 1.f + eg1;
    float do0 = 1.f + eo0, do1 = 1.f + eo1;
    float p01 = di0 * di1, p23 = df0 * df1, p45 = dg0 * dg1, p67 = do0 * do1;
    float q0 = p01 * p23, q1 = p45 * p67;
    float R  = rcpa(q0 * q1);
    float iq0 = R * q1, iq1 = R * q0;               // 1/q0, 1/q1
    float ip01 = iq0 * p23, ip23 = iq0 * p01;       // 1/p01, 1/p23
    float ip45 = iq1 * p67, ip67 = iq1 * p45;       // 1/p45, 1/p67
    float i0 = ip01 * di1, i1 = ip01 * di0;         // sigmoid(zi)
    float f0 = ip23 * df1, f1 = ip23 * df0;
    float go0 = ip45 * dg1, go1 = ip45 * dg0;       // 1/dg
    float o0 = ip67 * do1, o1 = ip67 * do0;
    float tg0 = copysignf((1.f - eg0) * go0, zg.x); // tanh(zg)
    float tg1 = copysignf((1.f - eg1) * go1, zg.y);
    cc0 = f0 * cc0 + i0 * tg0;
    cc1 = f1 * cc1 + i1 * tg1;
    float ec0 = ex2a(fabsf(cc0) * N2L2E), ec1 = ex2a(fabsf(cc1) * N2L2E);
    float dc0 = 1.f + ec0, dc1 = 1.f + ec1;
    float Rc = rcpa(dc0 * dc1);
    float tc0 = copysignf((1.f - ec0) * (Rc * dc1), cc0);
    float tc1 = copysignf((1.f - ec1) * (Rc * dc0), cc1);
    float2 h; h.x = o0 * tc0; h.y = o1 * tc1;
    return h;
}

// ---------------- cp.async / barrier helpers ----------------
__device__ __forceinline__ void cp16(uint32_t saddr, const float* g) {
    asm volatile("cp.async.cg.shared.global [%0], [%1], 16;" :: "r"(saddr), "l"(g));
}
__device__ __forceinline__ void cp_commit() { asm volatile("cp.async.commit_group;"); }
__device__ __forceinline__ void cp_wait0()  { asm volatile("cp.async.wait_group 0;" ::: "memory"); }
__device__ __forceinline__ void quad_bar(int id) {
    asm volatile("bar.sync %0, 128;" :: "r"(id) : "memory");
}

// 48-column panel: R rows x (2 units x 4 gates), quad-split weights
// (2x LDS.128 per k) + float4 input loads (R5-proven).
template <int R, int WK>
__device__ __forceinline__ void panelQ(ull (&acc)[R][4],
                                       const float* __restrict__ in,
                                       const float* __restrict__ wA,
                                       const float* __restrict__ wB) {
#pragma unroll 2
    for (int k = 0; k < 48; k += 4) {
        float4 a[R];
#pragma unroll
        for (int r = 0; r < R; r++) a[r] = *(const float4*)(in + r * RSTRIDE + k);
#pragma unroll
        for (int kk = 0; kk < 4; kk++) {
            ulonglong2 qa = *(const ulonglong2*)(wA + (k + kk) * WK);
            ulonglong2 qb = *(const ulonglong2*)(wB + (k + kk) * WK);
#pragma unroll
            for (int r = 0; r < R; r++) {
                float av = (kk == 0) ? a[r].x : (kk == 1) ? a[r].y : (kk == 2) ? a[r].z : a[r].w;
                ull p = pack2(av);
                acc[r][0] = fma2(p, qa.x, acc[r][0]);
                acc[r][1] = fma2(p, qa.y, acc[r][1]);
                acc[r][2] = fma2(p, qb.x, acc[r][2]);
                acc[r][3] = fma2(p, qb.y, acc[r][3]);
            }
        }
    }
}

__global__ void __launch_bounds__(THREADS, 1)
lstm_fused_kernel(const float* __restrict__ x,
                  const float* __restrict__ W1, const float* __restrict__ U1w, const float* __restrict__ b1,
                  const float* __restrict__ W2, const float* __restrict__ U2w, const float* __restrict__ b2,
                  const float* __restrict__ Wv, const float* __restrict__ bv,
                  const float* __restrict__ Wo, const float* __restrict__ bo,
                  const float* __restrict__ Wd1, const float* __restrict__ bd1,
                  const float* __restrict__ Wd2, const float* __restrict__ bd2,
                  float* __restrict__ out) {
    extern __shared__ float sm[];
    const int tid = threadIdx.x;
    const int b0  = blockIdx.x * ROWS;

    // ---- stage weights into quad-split interleaved SMEM arrays (one time) ----
    for (int idx = tid; idx < 96 * 32; idx += THREADS) {
        int k = idx >> 5, u = idx & 31;
        const float* src = (k < NFEAT) ? (W1 + k * G1) : (U1w + (k - NFEAT) * G1);
        float4 qa = make_float4(src[2 * u], src[2 * u + 1],
                                src[UN1 + 2 * u], src[UN1 + 2 * u + 1]);
        float4 qb = make_float4(src[2 * UN1 + 2 * u], src[2 * UN1 + 2 * u + 1],
                                src[3 * UN1 + 2 * u], src[3 * UN1 + 2 * u + 1]);
        ((float4*)(sm + OFF_W1A))[k * 32 + u] = qa;
        ((float4*)(sm + OFF_W1B))[k * 32 + u] = qb;
    }
    for (int idx = tid; idx < 96 * 16; idx += THREADS) {
        int k = idx >> 4, u = idx & 15;
        const float* src = (k < UN1) ? (W2 + k * G2) : (U2w + (k - UN1) * G2);
        float4 qa = make_float4(src[2 * u], src[2 * u + 1],
                                src[UN2 + 2 * u], src[UN2 + 2 * u + 1]);
        float4 qb = make_float4(src[2 * UN2 + 2 * u], src[2 * UN2 + 2 * u + 1],
                                src[3 * UN2 + 2 * u], src[3 * UN2 + 2 * u + 1]);
        ((float4*)(sm + OFF_W2A))[k * 16 + u] = qa;
        ((float4*)(sm + OFF_W2B))[k * 16 + u] = qb;
    }
    for (int i = tid; i < 2 * ROWS * RSTRIDE; i += THREADS) sm[OFF_C + i] = 0.0f;

    // ---- quad mapping: quad q = warps {q, q+4, q+8, q+12}, ALL on SMSP q ----
    // roles: 0,1 = L1 up-halves (8-row tile, rows q*8..q*8+7)
    //        2,3 = L2 (4-row tiles, rows q*8+{0..3} / q*8+{4..7})
    const int wid  = tid >> 5;
    const int l    = tid & 31;
    const int q    = wid & 3;          // quad == SMSP
    const int role = wid >> 2;         // 0..3
    const bool isL1 = (role < 2);
    const int kh   = l >> 4;           // K-half split within warp
    const int rg   = q;                            // L1 row group (8 rows)
    const int up   = (l & 15) | (role << 4);       // L1 unit pair 0..31
    const int rg2  = 2 * q + (role - 2);           // L2 row group (4 rows)
    const int up2  = l & 15;                       // L2 unit pair 0..15

    // bias -> registers (kh==0 half carries it; partner contributes 0)
    ull bq[4];
    if (isL1) {
#pragma unroll
        for (int g = 0; g < 4; g++) {
            float2 bb = (kh == 0) ? *(const float2*)(b1 + g * UN1 + 2 * up)
                                  : make_float2(0.f, 0.f);
            bq[g] = pakf2(bb.x, bb.y);
        }
    } else {
#pragma unroll
        for (int g = 0; g < 4; g++) {
            float2 bb = (kh == 0) ? *(const float2*)(b2 + g * UN2 + 2 * up2)
                                  : make_float2(0.f, 0.f);
            bq[g] = pakf2(bb.x, bb.y);
        }
    }

    float c1[4][2], c2[2][2];
#pragma unroll
    for (int r = 0; r < 4; r++) { c1[r][0] = c1[r][1] = 0.0f; }
#pragma unroll
    for (int r = 0; r < 2; r++) { c2[r][0] = c2[r][1] = 0.0f; }

    // ---- x prefetch: quad-local. Movers = the quad's 2 L1 warps (64 threads),
    // each moves one float4 of the quad's own 8 rows per step.
    const bool xmover = isL1;
    const int m    = (role << 5) | l;          // 0..63 within the L1 pair
    const int xrow = q * 8 + (m >> 3);         // this quad's rows
    const int xq   = m & 7;
    const float* xg = x + ((size_t)(b0 + xrow) * T_STEPS) * NFEAT + xq * 4;
    uint32_t sx0 = (uint32_t)__cvta_generic_to_shared(sm + OFF_C + xrow * RSTRIDE + xq * 4);
    const uint32_t cbufbytes = ROWS * RSTRIDE * 4;

    __syncthreads();                    // weights + zeroed state visible CTA-wide
    if (xmover) cp16(sx0, xg);          // x_0 -> buffer 0
    cp_commit();

    const float* wA1 = sm + OFF_W1A + (kh * 48) * WK1 + up * 4;
    const float* wB1 = sm + OFF_W1B + (kh * 48) * WK1 + up * 4;
    const float* wA2 = sm + OFF_W2A + (kh * 48) * WK2 + up2 * 4;
    const float* wB2 = sm + OFF_W2B + (kh * 48) * WK2 + up2 * 4;

    // Iter t: L1 computes step t (t<T), L2 computes step t-1 (t>=1).
    // One PER-QUAD barrier per step (dataflow is quad-local).
    for (int t = 0; t <= T_STEPS; ++t) {
        if (t < T_STEPS) cp_wait0();   // movers observe x_t completion
        quad_bar(q + 1);               // quad-wide: x_t + h1/h2 writes visible
        if (t + 1 < T_STEPS && xmover)
            cp16(sx0 + ((t + 1) & 1) * cbufbytes, xg + (size_t)(t + 1) * NFEAT);
        cp_commit();
        const int rb = t & 1;
        const float* cin  = sm + OFF_C + rb * (ROWS * RSTRIDE);
        float*       cout = sm + OFF_C + (rb ^ 1) * (ROWS * RSTRIDE);

        if (isL1) {
            if (t < T_STEPS) {
                ull acc[8][4];
#pragma unroll
                for (int r = 0; r < 8; r++)
#pragma unroll
                    for (int g = 0; g < 4; g++) acc[r][g] = bq[g];

                // gate K-rows [x|h1] = cin cols 0..95; this thread: cols kh*48..+47
                panelQ<8, WK1>(acc, cin + rg * 8 * RSTRIDE + kh * 48, wA1, wB1);

                // symmetric K-split reduction (static indexing)
#pragma unroll
                for (int r = 0; r < 8; r++)
#pragma unroll
                    for (int g = 0; g < 4; g++)
                        acc[r][g] = add2(acc[r][g], __shfl_xor_sync(0xffffffffu, acc[r][g], 16));

                // kh=0 activates rows 0..3; kh=1 rows 4..7
#pragma unroll
                for (int r = 0; r < 4; r++) {
                    float2 zi = unpack2(kh ? acc[r + 4][0] : acc[r][0]);
                    float2 zf = unpack2(kh ? acc[r + 4][1] : acc[r][1]);
                    float2 zg = unpack2(kh ? acc[r + 4][2] : acc[r][2]);
                    float2 zo = unpack2(kh ? acc[r + 4][3] : acc[r][3]);
                    float2 h = lstm_act2(zi, zf, zg, zo, c1[r][0], c1[r][1]);
                    *(float2*)(cout + (rg * 8 + kh * 4 + r) * RSTRIDE + 32 + 2 * up) = h;
                }
            }
        } else {
            if (t >= 1) {
                ull acc2[4][4];
#pragma unroll
                for (int r = 0; r < 4; r++)
#pragma unroll
                    for (int g = 0; g < 4; g++) acc2[r][g] = bq[g];

                // gate K-rows [h1(t-1)|h2(t-2)] = cin cols 32..127; this thread: 32+kh*48..+47
                panelQ<4, WK2>(acc2, cin + rg2 * 4 * RSTRIDE + 32 + kh * 48, wA2, wB2);

#pragma unroll
                for (int r = 0; r < 4; r++)
#pragma unroll
                    for (int g = 0; g < 4; g++)
                        acc2[r][g] = add2(acc2[r][g], __shfl_xor_sync(0xffffffffu, acc2[r][g], 16));

#pragma unroll
                for (int r = 0; r < 2; r++) {
                    float2 zi = unpack2(kh ? acc2[r + 2][0] : acc2[r][0]);
                    float2 zf = unpack2(kh ? acc2[r + 2][1] : acc2[r][1]);
                    float2 zg = unpack2(kh ? acc2[r + 2][2] : acc2[r][2]);
                    float2 zo = unpack2(kh ? acc2[r + 2][3] : acc2[r][3]);
                    float2 h = lstm_act2(zi, zf, zg, zo, c2[r][0], c2[r][1]);
                    *(float2*)(cout + (rg2 * 4 + kh * 2 + r) * RSTRIDE + 96 + 2 * up2) = h;
                }
            }
        }
    }
    __syncthreads();   // all quads done; h2 visible CTA-wide

    // final h2 = h2(T-1), written at iter t=T into buf ((T&1)^1)
    const float* h2f = sm + OFF_C + ((T_STEPS & 1) ^ 1) * (ROWS * RSTRIDE) + 96;

    // ============ head: MHA(seq=1) == identity-attention -> v@Wo, then MLP ============
    float* sv  = sm;            // scratch in dead weight region
    float* so  = sm + 1024;
    float* sd1 = sm + 2048;
    for (int idx = tid; idx < ROWS * 32; idx += THREADS) {
        int r = idx >> 5, j = idx & 31;
        float s = bv[j];
        const float* h2row = h2f + r * RSTRIDE;
#pragma unroll
        for (int d = 0; d < 32; d++) s += h2row[d] * Wv[d * 32 + j];
        sv[idx] = s;
    }
    __syncthreads();
    for (int idx = tid; idx < ROWS * 32; idx += THREADS) {
        int r = idx >> 5, e = idx & 31;
        float s = bo[e];
#pragma unroll
        for (int j = 0; j < 32; j++) s += sv[r * 32 + j] * Wo[j * 32 + e];
        so[idx] = s;
    }
    __syncthreads();
    for (int idx = tid; idx < ROWS * 64; idx += THREADS) {
        int r = idx >> 6, m2 = idx & 63;
        float s = bd1[m2];
#pragma unroll
        for (int e = 0; e < 32; e++) s += so[r * 32 + e] * Wd1[e * 64 + m2];
        sd1[idx] = fmaxf(s, 0.0f);
    }
    __syncthreads();
    for (int idx = tid; idx < ROWS * 24; idx += THREADS) {
        int r = idx / 24, p = idx % 24;
        float s = bd2[p];
#pragma unroll
        for (int m2 = 0; m2 < 64; m2++) s += sd1[r * 64 + m2] * Wd2[m2 * 24 + p];
        out[(size_t)(b0 + r) * 24 + p] = s;
    }
}

extern "C" void kernel_launch(void* const* d_in, const int* in_sizes, int n_in,
                              void* d_out, int out_size) {
    const float* x   = (const float*)d_in[0];
    const float* W1  = (const float*)d_in[1];
    const float* U1w = (const float*)d_in[2];
    const float* b1  = (const float*)d_in[3];
    const float* W2  = (const float*)d_in[4];
    const float* U2w = (const float*)d_in[5];
    const float* b2  = (const float*)d_in[6];
    // d_in[7..10] = Wq, bq, Wk, bk: dead (softmax over seq-len 1 == 1)
    const float* Wv  = (const float*)d_in[11];
    const float* bv  = (const float*)d_in[12];
    const float* Wo  = (const float*)d_in[13];
    const float* bo  = (const float*)d_in[14];
    const float* Wd1 = (const float*)d_in[15];
    const float* bd1 = (const float*)d_in[16];
    const float* Wd2 = (const float*)d_in[17];
    const float* bd2 = (const float*)d_in[18];

    size_t smem = SMEM_FLOATS * sizeof(float);   // 180224 B
    cudaFuncSetAttribute(lstm_fused_kernel,
                         cudaFuncAttributeMaxDynamicSharedMemorySize, (int)smem);
    lstm_fused_kernel<<<CTAS, THREADS, smem>>>(
        x, W1, U1w, b1, W2, U2w, b2, Wv, bv, Wo, bo, Wd1, bd1, Wd2, bd2,
        (float*)d_out);
}